// round 1
// baseline (speedup 1.0000x reference)
#include <cuda_runtime.h>
#include <math.h>

// Problem constants
#define BB 4
#define CH 1024
#define WW 2048
#define OC 512      // CH/2
#define C8 128      // CH/8
#define PW 1024     // pooled width (WW/2)
#define WP 512      // WW/4
#define NSQ 10      // Gram squarings -> exponent 2^10

// ---------------- scratch (static device memory; no allocations) ----------------
__device__ float d_theta [BB*C8*WW];
__device__ float d_phiraw[BB*C8*WW];
__device__ float d_graw  [BB*OC*WW];
__device__ float d_phip  [BB*C8*WP];   // flat [b][65536]
__device__ float d_gp    [BB*OC*WP];   // flat [b][262144]
__device__ float d_attn  [BB*WW*WP];
__device__ float d_attng [BB*OC*WW];
__device__ float d_x     [BB*CH*WW];
__device__ float d_h1    [BB*OC*WW];
__device__ float d_h2    [BB*OC*WW];

#define GTOT (2*128*128 + 2*512*512)
__device__ float    d_g0[GTOT];
__device__ float    d_ga[GTOT];
__device__ float    d_gb[GTOT];
__device__ unsigned d_maxd[(NSQ+1)*4];
__device__ float    d_invsig[4];

__device__ __forceinline__ int gram_m(int z)   { return (z < 2) ? 128 : 512; }
__device__ __forceinline__ int gram_off(int z) {
    return (z == 0) ? 0 : (z == 1) ? 16384 : (z == 2) ? 32768 : 294912;
}
__device__ __forceinline__ void amaxf(unsigned* p, float v) {
    atomicMax(p, __float_as_uint(v));  // valid for non-negative floats
}

// ---------------- spectral norm chain ----------------
__global__ void init_k() {
    int t = threadIdx.x;
    if (t < (NSQ + 1) * 4) d_maxd[t] = 0u;
}

// G0 = W W^T (z=0,1,2: W is [m,1024] row-major) or W^T W (z=3: W is [1024,512])
__global__ __launch_bounds__(256) void gram_k(const float* w0, const float* w1,
                                              const float* w2, const float* w3) {
    int z = blockIdx.z;
    int m = gram_m(z), nt = m >> 5;
    if (blockIdx.x >= nt || blockIdx.y >= nt) return;
    const float* wp = (z == 0) ? w0 : (z == 1) ? w1 : (z == 2) ? w2 : w3;
    int goff = gram_off(z);
    int i0 = blockIdx.y * 32, j0 = blockIdx.x * 32;
    int tid = threadIdx.x, tx = tid & 15, ty = tid >> 4;
    __shared__ float As[32][33], Bs[32][33];
    float acc[2][2] = {{0.f,0.f},{0.f,0.f}};
    for (int k0 = 0; k0 < 1024; k0 += 32) {
        if (z < 3) {
            for (int idx = tid; idx < 1024; idx += 256) {
                int kk = idx & 31, mm = idx >> 5;
                As[mm][kk] = wp[(i0 + mm) * 1024 + k0 + kk];
                Bs[mm][kk] = wp[(j0 + mm) * 1024 + k0 + kk];
            }
        } else {
            for (int idx = tid; idx < 1024; idx += 256) {
                int mm = idx & 31, kk = idx >> 5;
                As[mm][kk] = wp[(k0 + kk) * 512 + i0 + mm];
                Bs[mm][kk] = wp[(k0 + kk) * 512 + j0 + mm];
            }
        }
        __syncthreads();
        #pragma unroll
        for (int kk = 0; kk < 32; kk++) {
            float a0 = As[ty][kk], a1 = As[ty + 16][kk];
            float b0 = Bs[tx][kk], b1 = Bs[tx + 16][kk];
            acc[0][0] += a0 * b0; acc[0][1] += a0 * b1;
            acc[1][0] += a1 * b0; acc[1][1] += a1 * b1;
        }
        __syncthreads();
    }
    #pragma unroll
    for (int a = 0; a < 2; a++)
    #pragma unroll
    for (int b = 0; b < 2; b++) {
        int i = i0 + ty + 16 * a, j = j0 + tx + 16 * b;
        float v = acc[a][b];
        d_g0[goff + i * m + j] = v;
        if (i == j) amaxf(&d_maxd[z], v);
    }
}

// H_{t+1} = (H_t / s)^2 ; s = maxdiag(H_t). Symmetric, so H*H == H*H^T (row-row form).
__global__ __launch_bounds__(256) void square_k(int t) {
    int z = blockIdx.z;
    int m = gram_m(z), nt = m >> 5;
    if (blockIdx.x >= nt || blockIdx.y >= nt) return;
    int goff = gram_off(z);
    const float* in = ((t == 0) ? d_g0 : ((t & 1) ? d_ga : d_gb)) + goff;
    float* out = (((t & 1) ? d_gb : d_ga)) + goff;
    float s = __uint_as_float(d_maxd[t * 4 + z]);
    float isc = 1.0f / (s * s);
    int i0 = blockIdx.y * 32, j0 = blockIdx.x * 32;
    int tid = threadIdx.x, tx = tid & 15, ty = tid >> 4;
    __shared__ float As[32][33], Bs[32][33];
    float acc[2][2] = {{0.f,0.f},{0.f,0.f}};
    for (int k0 = 0; k0 < m; k0 += 32) {
        for (int idx = tid; idx < 1024; idx += 256) {
            int kk = idx & 31, mm = idx >> 5;
            As[mm][kk] = in[(i0 + mm) * m + k0 + kk];
            Bs[mm][kk] = in[(j0 + mm) * m + k0 + kk];
        }
        __syncthreads();
        #pragma unroll
        for (int kk = 0; kk < 32; kk++) {
            float a0 = As[ty][kk], a1 = As[ty + 16][kk];
            float b0 = Bs[tx][kk], b1 = Bs[tx + 16][kk];
            acc[0][0] += a0 * b0; acc[0][1] += a0 * b1;
            acc[1][0] += a1 * b0; acc[1][1] += a1 * b1;
        }
        __syncthreads();
    }
    #pragma unroll
    for (int a = 0; a < 2; a++)
    #pragma unroll
    for (int b = 0; b < 2; b++) {
        int i = i0 + ty + 16 * a, j = j0 + tx + 16 * b;
        float v = acc[a][b] * isc;
        out[i * m + j] = v;
        if (i == j) amaxf(&d_maxd[(t + 1) * 4 + z], v);
    }
}

// sigma^2 = (v^T G0 v)/(v^T v) with v = column of H_final at argmax diag.
__global__ void rayleigh_k() {
    int z = blockIdx.x;
    int m = gram_m(z), goff = gram_off(z);
    const float* H  = d_gb + goff;   // NSQ even -> final in d_gb
    const float* G0 = d_g0 + goff;
    int tid = threadIdx.x, lane = tid & 31, w = tid >> 5;
    __shared__ float sval[16]; __shared__ int sidx[16];
    float best = -1.f; int bi = 0;
    for (int i = tid; i < m; i += 512) {
        float d = H[i * m + i];
        if (d > best) { best = d; bi = i; }
    }
    #pragma unroll
    for (int off = 16; off; off >>= 1) {
        float ov = __shfl_xor_sync(0xffffffffu, best, off);
        int   oi = __shfl_xor_sync(0xffffffffu, bi,   off);
        if (ov > best || (ov == best && oi < bi)) { best = ov; bi = oi; }
    }
    if (lane == 0) { sval[w] = best; sidx[w] = bi; }
    __syncthreads();
    if (tid == 0) {
        float bb = sval[0]; int bj = sidx[0];
        for (int i = 1; i < 16; i++)
            if (sval[i] > bb || (sval[i] == bb && sidx[i] < bj)) { bb = sval[i]; bj = sidx[i]; }
        sidx[0] = bj;
    }
    __syncthreads();
    int js = sidx[0];
    __shared__ float sv[512];
    for (int i = tid; i < m; i += 512) sv[i] = H[i * m + js];
    __syncthreads();
    __shared__ float snum[16], sden[16];
    float numacc = 0.f, denacc = 0.f;
    for (int i = w; i < m; i += 16) {
        float u = 0.f;
        for (int j = lane; j < m; j += 32) u += G0[i * m + j] * sv[j];
        #pragma unroll
        for (int off = 16; off; off >>= 1) u += __shfl_xor_sync(0xffffffffu, u, off);
        if (lane == 0) { numacc += sv[i] * u; denacc += sv[i] * sv[i]; }
    }
    if (lane == 0) { snum[w] = numacc; sden[w] = denacc; }
    __syncthreads();
    if (tid == 0) {
        float n = 0.f, d = 0.f;
        for (int i = 0; i < 16; i++) { n += snum[i]; d += sden[i]; }
        d_invsig[z] = sqrtf(d / n);
    }
}

// ---------------- fused theta/phi/g projection: out = (invsig*W) @ src ----------------
__global__ __launch_bounds__(256) void qkv_k(const float* __restrict__ src,
                                             const float* __restrict__ wt,
                                             const float* __restrict__ wf,
                                             const float* __restrict__ wg) {
    int b = blockIdx.z, mt = blockIdx.y;
    const float* wp; float* op; int row0, nrows; float sc;
    if (mt < 2)      { wp = wt; row0 = mt * 64;        sc = d_invsig[0]; op = d_theta;  nrows = C8; }
    else if (mt < 4) { wp = wf; row0 = (mt - 2) * 64;  sc = d_invsig[1]; op = d_phiraw; nrows = C8; }
    else             { wp = wg; row0 = (mt - 4) * 64;  sc = d_invsig[2]; op = d_graw;   nrows = OC; }
    int n0 = blockIdx.x * 64;
    int tid = threadIdx.x, tx = tid & 15, ty = tid >> 4;
    __shared__ float As[16][65], Bs[16][65];
    float acc[4][4] = {};
    const float* sb = src + (size_t)b * CH * WW;
    for (int k0 = 0; k0 < 1024; k0 += 16) {
        for (int idx = tid; idx < 1024; idx += 256) {
            int kk = idx & 15, mm = idx >> 4;
            As[kk][mm] = wp[(row0 + mm) * 1024 + k0 + kk] * sc;
        }
        for (int idx = tid; idx < 1024; idx += 256) {
            int nn = idx & 63, kk = idx >> 6;
            Bs[kk][nn] = sb[(k0 + kk) * WW + n0 + nn];
        }
        __syncthreads();
        #pragma unroll
        for (int kk = 0; kk < 16; kk++) {
            float a[4], bb[4];
            #pragma unroll
            for (int i = 0; i < 4; i++) a[i]  = As[kk][ty + 16 * i];
            #pragma unroll
            for (int j = 0; j < 4; j++) bb[j] = Bs[kk][tx + 16 * j];
            #pragma unroll
            for (int i = 0; i < 4; i++)
            #pragma unroll
            for (int j = 0; j < 4; j++) acc[i][j] += a[i] * bb[j];
        }
        __syncthreads();
    }
    float* ob = op + (size_t)b * nrows * WW;
    #pragma unroll
    for (int i = 0; i < 4; i++)
    #pragma unroll
    for (int j = 0; j < 4; j++)
        ob[(row0 + ty + 16 * i) * WW + n0 + tx + 16 * j] = acc[i][j];
}

// maxpool 2x2 over (c,w); sel 0 = phi (C=128), 1 = g (C=512)
__global__ void pool_k(int sel) {
    int gid = blockIdx.x * 256 + threadIdx.x;
    int inC = sel ? OC : C8;
    const float* in = sel ? d_graw : d_phiraw;
    float* out = sel ? d_gp : d_phip;
    int per = (inC / 2) * PW;
    if (gid >= BB * per) return;
    int b = gid / per, r = gid - b * per;
    int cp = r / PW, wp = r - cp * PW;
    const float* p = in + (size_t)b * inC * WW + (size_t)(2 * cp) * WW + 2 * wp;
    out[gid] = fmaxf(fmaxf(p[0], p[1]), fmaxf(p[WW], p[WW + 1]));
}

// scores S[b,w,v] = sum_c theta[b,c,w] * phip[b, c*512+v]
__global__ __launch_bounds__(256) void scores_k() {
    int b = blockIdx.z;
    int m0 = blockIdx.y * 64, n0 = blockIdx.x * 64;
    int tid = threadIdx.x, tx = tid & 15, ty = tid >> 4;
    const float* tb = d_theta + (size_t)b * C8 * WW;
    const float* pb = d_phip  + (size_t)b * C8 * WP;
    __shared__ float As[16][65], Bs[16][65];
    float acc[4][4] = {};
    for (int k0 = 0; k0 < 128; k0 += 16) {
        for (int idx = tid; idx < 1024; idx += 256) {
            int mm = idx & 63, kk = idx >> 6;
            As[kk][mm] = tb[(k0 + kk) * WW + m0 + mm];
        }
        for (int idx = tid; idx < 1024; idx += 256) {
            int nn = idx & 63, kk = idx >> 6;
            Bs[kk][nn] = pb[(k0 + kk) * WP + n0 + nn];
        }
        __syncthreads();
        #pragma unroll
        for (int kk = 0; kk < 16; kk++) {
            float a[4], bb[4];
            #pragma unroll
            for (int i = 0; i < 4; i++) a[i]  = As[kk][ty + 16 * i];
            #pragma unroll
            for (int j = 0; j < 4; j++) bb[j] = Bs[kk][tx + 16 * j];
            #pragma unroll
            for (int i = 0; i < 4; i++)
            #pragma unroll
            for (int j = 0; j < 4; j++) acc[i][j] += a[i] * bb[j];
        }
        __syncthreads();
    }
    float* ob = d_attn + (size_t)b * WW * WP;
    #pragma unroll
    for (int i = 0; i < 4; i++)
    #pragma unroll
    for (int j = 0; j < 4; j++)
        ob[(m0 + ty + 16 * i) * WP + n0 + tx + 16 * j] = acc[i][j];
}

__global__ __launch_bounds__(128) void softmax_k() {
    int row = blockIdx.x;                 // 0..8191
    float* p = d_attn + (size_t)row * WP;
    int t = threadIdx.x, lane = t & 31, w = t >> 5;
    float v0 = p[t], v1 = p[t + 128], v2 = p[t + 256], v3 = p[t + 384];
    float mx = fmaxf(fmaxf(v0, v1), fmaxf(v2, v3));
    __shared__ float sm[4];
    #pragma unroll
    for (int off = 16; off; off >>= 1) mx = fmaxf(mx, __shfl_xor_sync(0xffffffffu, mx, off));
    if (lane == 0) sm[w] = mx;
    __syncthreads();
    mx = fmaxf(fmaxf(sm[0], sm[1]), fmaxf(sm[2], sm[3]));
    float e0 = expf(v0 - mx), e1 = expf(v1 - mx), e2 = expf(v2 - mx), e3 = expf(v3 - mx);
    float s = e0 + e1 + e2 + e3;
    #pragma unroll
    for (int off = 16; off; off >>= 1) s += __shfl_xor_sync(0xffffffffu, s, off);
    if (lane == 0) sm[w] = s;
    __syncthreads();
    float inv = 1.0f / (sm[0] + sm[1] + sm[2] + sm[3]);
    p[t] = e0 * inv; p[t + 128] = e1 * inv; p[t + 256] = e2 * inv; p[t + 384] = e3 * inv;
}

// attn_g[b,c,w] = sum_v gp[b, c*512+v] * attn[b, w, v]
__global__ __launch_bounds__(256) void attng_k() {
    int b = blockIdx.z;
    int m0 = blockIdx.y * 64, n0 = blockIdx.x * 64;
    int tid = threadIdx.x, tx = tid & 15, ty = tid >> 4;
    const float* gb = d_gp   + (size_t)b * OC * WP;
    const float* ab = d_attn + (size_t)b * WW * WP;
    __shared__ float As[16][65], Bs[16][65];
    float acc[4][4] = {};
    for (int k0 = 0; k0 < WP; k0 += 16) {
        for (int idx = tid; idx < 1024; idx += 256) {
            int kk = idx & 15, mm = idx >> 4;
            As[kk][mm] = gb[(m0 + mm) * WP + k0 + kk];
        }
        for (int idx = tid; idx < 1024; idx += 256) {
            int kk = idx & 15, nn = idx >> 4;
            Bs[kk][nn] = ab[(size_t)(n0 + nn) * WP + k0 + kk];
        }
        __syncthreads();
        #pragma unroll
        for (int kk = 0; kk < 16; kk++) {
            float a[4], bb[4];
            #pragma unroll
            for (int i = 0; i < 4; i++) a[i]  = As[kk][ty + 16 * i];
            #pragma unroll
            for (int j = 0; j < 4; j++) bb[j] = Bs[kk][tx + 16 * j];
            #pragma unroll
            for (int i = 0; i < 4; i++)
            #pragma unroll
            for (int j = 0; j < 4; j++) acc[i][j] += a[i] * bb[j];
        }
        __syncthreads();
    }
    float* ob = d_attng + (size_t)b * OC * WW;
    #pragma unroll
    for (int i = 0; i < 4; i++)
    #pragma unroll
    for (int j = 0; j < 4; j++)
        ob[(m0 + ty + 16 * i) * WW + n0 + tx + 16 * j] = acc[i][j];
}

// x = 2*src + gamma * ( (invsig3 * w_o) @ attn_g )
__global__ __launch_bounds__(256) void xo_k(const float* __restrict__ src,
                                            const float* __restrict__ wo,
                                            const float* __restrict__ gammap) {
    int b = blockIdx.z;
    int m0 = blockIdx.y * 64, n0 = blockIdx.x * 64;
    int tid = threadIdx.x, tx = tid & 15, ty = tid >> 4;
    float sc = d_invsig[3];
    float gm = gammap[0];
    const float* ab = d_attng + (size_t)b * OC * WW;
    __shared__ float As[16][65], Bs[16][65];
    float acc[4][4] = {};
    for (int k0 = 0; k0 < OC; k0 += 16) {
        for (int idx = tid; idx < 1024; idx += 256) {
            int kk = idx & 15, mm = idx >> 4;
            As[kk][mm] = wo[(m0 + mm) * OC + k0 + kk] * sc;
        }
        for (int idx = tid; idx < 1024; idx += 256) {
            int nn = idx & 63, kk = idx >> 6;
            Bs[kk][nn] = ab[(k0 + kk) * WW + n0 + nn];
        }
        __syncthreads();
        #pragma unroll
        for (int kk = 0; kk < 16; kk++) {
            float a[4], bb[4];
            #pragma unroll
            for (int i = 0; i < 4; i++) a[i]  = As[kk][ty + 16 * i];
            #pragma unroll
            for (int j = 0; j < 4; j++) bb[j] = Bs[kk][tx + 16 * j];
            #pragma unroll
            for (int i = 0; i < 4; i++)
            #pragma unroll
            for (int j = 0; j < 4; j++) acc[i][j] += a[i] * bb[j];
        }
        __syncthreads();
    }
    #pragma unroll
    for (int i = 0; i < 4; i++)
    #pragma unroll
    for (int j = 0; j < 4; j++) {
        size_t oi = (size_t)b * CH * WW + (size_t)(m0 + ty + 16 * i) * WW + n0 + tx + 16 * j;
        d_x[oi] = 2.0f * src[oi] + gm * acc[i][j];
    }
}

// conv1d K=3 'same' + ReLU (+ optional residual). insel: 0=d_x 1=d_h1 2=d_h2.
// outsel: 0=d_h1 1=d_h2 2=outext.
__global__ __launch_bounds__(256) void conv_k(int insel, const float* __restrict__ wgt,
                                              const float* __restrict__ bias,
                                              const float* __restrict__ resid,
                                              float* outext, int outsel,
                                              int IC, int OCn) {
    const float* in = (insel == 0) ? d_x : (insel == 1) ? d_h1 : d_h2;
    float* out = (outsel == 0) ? d_h1 : (outsel == 1) ? d_h2 : outext;
    int bz = blockIdx.z;
    int o0 = blockIdx.y * 64, w0 = blockIdx.x * 64;
    int tid = threadIdx.x, tx = tid & 15, ty = tid >> 4;
    __shared__ float xs[16][72];   // 66 used (halo), padded
    __shared__ float ws[64][48];   // 16 ic * 3 taps
    float acc[4][4] = {};
    const float* inb = in + (size_t)bz * IC * WW;
    for (int ic0 = 0; ic0 < IC; ic0 += 16) {
        for (int idx = tid; idx < 16 * 66; idx += 256) {
            int r = idx / 66, c = idx - r * 66;
            int wsrc = w0 + c - 1;
            xs[r][c] = (wsrc >= 0 && wsrc < WW) ? inb[(size_t)(ic0 + r) * WW + wsrc] : 0.0f;
        }
        for (int idx = tid; idx < 64 * 48; idx += 256) {
            int oo = idx / 48, q = idx - oo * 48;
            ws[oo][q] = wgt[(size_t)(o0 + oo) * IC * 3 + ic0 * 3 + q];
        }
        __syncthreads();
        #pragma unroll
        for (int ic = 0; ic < 16; ic++) {
            float wv0[4], wv1[4], wv2[4];
            #pragma unroll
            for (int a = 0; a < 4; a++) {
                wv0[a] = ws[ty + 16 * a][ic * 3 + 0];
                wv1[a] = ws[ty + 16 * a][ic * 3 + 1];
                wv2[a] = ws[ty + 16 * a][ic * 3 + 2];
            }
            #pragma unroll
            for (int b2 = 0; b2 < 4; b2++) {
                float x0 = xs[ic][tx + 16 * b2];
                float x1 = xs[ic][tx + 16 * b2 + 1];
                float x2 = xs[ic][tx + 16 * b2 + 2];
                #pragma unroll
                for (int a = 0; a < 4; a++)
                    acc[a][b2] += wv0[a] * x0 + wv1[a] * x1 + wv2[a] * x2;
            }
        }
        __syncthreads();
    }
    #pragma unroll
    for (int a = 0; a < 4; a++) {
        int o = o0 + ty + 16 * a;
        float bi = bias[o];
        #pragma unroll
        for (int b2 = 0; b2 < 4; b2++) {
            int wi = w0 + tx + 16 * b2;
            float v = fmaxf(acc[a][b2] + bi, 0.0f);
            size_t oi = (size_t)bz * OCn * WW + (size_t)o * WW + wi;
            if (resid) v += resid[oi];
            out[oi] = v;
        }
    }
}

// ---------------- launch ----------------
extern "C" void kernel_launch(void* const* d_in, const int* in_sizes, int n_in,
                              void* d_out, int out_size) {
    const float* src     = (const float*)d_in[0];
    const float* w_theta = (const float*)d_in[1];
    const float* w_phi   = (const float*)d_in[2];
    const float* w_g     = (const float*)d_in[3];
    const float* w_o     = (const float*)d_in[4];
    const float* gamma   = (const float*)d_in[5];
    const float* w_c1    = (const float*)d_in[6];
    const float* b_c1    = (const float*)d_in[7];
    const float* w_c2    = (const float*)d_in[8];
    const float* b_c2    = (const float*)d_in[9];
    const float* w_c3    = (const float*)d_in[10];
    const float* b_c3    = (const float*)d_in[11];
    const float* w_c4    = (const float*)d_in[12];
    const float* b_c4    = (const float*)d_in[13];
    float* out = (float*)d_out;

    // spectral norms
    init_k<<<1, 64>>>();
    gram_k<<<dim3(16, 16, 4), 256>>>(w_theta, w_phi, w_g, w_o);
    for (int t = 0; t < NSQ; t++)
        square_k<<<dim3(16, 16, 4), 256>>>(t);
    rayleigh_k<<<4, 512>>>();

    // attention
    qkv_k<<<dim3(32, 12, 4), 256>>>(src, w_theta, w_phi, w_g);
    pool_k<<<(BB * (C8 / 2) * PW + 255) / 256, 256>>>(0);   // phi
    pool_k<<<(BB * (OC / 2) * PW + 255) / 256, 256>>>(1);   // g
    scores_k<<<dim3(WP / 64, WW / 64, 4), 256>>>();
    softmax_k<<<BB * WW, 128>>>();
    attng_k<<<dim3(WW / 64, OC / 64, 4), 256>>>();
    xo_k<<<dim3(WW / 64, CH / 64, 4), 256>>>(src, w_o, gamma);

    // conv FFN
    conv_k<<<dim3(WW / 64, OC / 64, 4), 256>>>(0, w_c1, b_c1, nullptr, nullptr, 0, CH, OC);
    conv_k<<<dim3(WW / 64, OC / 64, 4), 256>>>(1, w_c2, b_c2, nullptr, nullptr, 1, OC, OC);
    conv_k<<<dim3(WW / 64, OC / 64, 4), 256>>>(2, w_c3, b_c3, nullptr, nullptr, 0, OC, OC);
    conv_k<<<dim3(WW / 64, CH / 64, 4), 256>>>(1, w_c4, b_c4, src, out, 2, OC, CH);
}

// round 2
// speedup vs baseline: 1.0016x; 1.0016x over previous
#include <cuda_runtime.h>
#include <math.h>

// Problem constants
#define BB 4
#define CH 1024
#define WW 2048
#define OC 512      // CH/2
#define C8 128      // CH/8
#define PW 1024     // pooled width (WW/2)
#define WP 512      // WW/4
#define NSQ 10      // Gram squarings -> exponent 2^10

// ---------------- scratch (static device memory; no allocations) ----------------
__device__ float d_theta [BB*C8*WW];
__device__ float d_phiraw[BB*C8*WW];
__device__ float d_graw  [BB*OC*WW];
__device__ float d_phip  [BB*C8*WP];   // flat [b][65536]
__device__ float d_gp    [BB*OC*WP];   // flat [b][262144]
__device__ float d_attn  [BB*WW*WP];
__device__ float d_attng [BB*OC*WW];
__device__ float d_x     [BB*CH*WW];
__device__ float d_h1    [BB*OC*WW];
__device__ float d_h2    [BB*OC*WW];

#define GTOT (2*128*128 + 2*512*512)
__device__ float    d_g0[GTOT];
__device__ float    d_ga[GTOT];
__device__ float    d_gb[GTOT];
__device__ unsigned d_maxd[(NSQ+1)*4];
__device__ float    d_invsig[4];

__device__ __forceinline__ int gram_m(int z)   { return (z < 2) ? 128 : 512; }
__device__ __forceinline__ int gram_off(int z) {
    return (z == 0) ? 0 : (z == 1) ? 16384 : (z == 2) ? 32768 : 294912;
}
__device__ __forceinline__ void amaxf(unsigned* p, float v) {
    atomicMax(p, __float_as_uint(v));  // valid for non-negative floats
}

// ---------------- spectral norm chain ----------------
__global__ void init_k() {
    int t = threadIdx.x;
    if (t < (NSQ + 1) * 4) d_maxd[t] = 0u;
}

// G0 = W W^T (z=0,1,2: W is [m,1024] row-major) or W^T W (z=3: W is [1024,512])
__global__ __launch_bounds__(256) void gram_k(const float* w0, const float* w1,
                                              const float* w2, const float* w3) {
    int z = blockIdx.z;
    int m = gram_m(z), nt = m >> 5;
    if (blockIdx.x >= nt || blockIdx.y >= nt) return;
    const float* wp = (z == 0) ? w0 : (z == 1) ? w1 : (z == 2) ? w2 : w3;
    int goff = gram_off(z);
    int i0 = blockIdx.y * 32, j0 = blockIdx.x * 32;
    int tid = threadIdx.x, tx = tid & 15, ty = tid >> 4;
    __shared__ float As[32][33], Bs[32][33];
    float acc[2][2] = {{0.f,0.f},{0.f,0.f}};
    for (int k0 = 0; k0 < 1024; k0 += 32) {
        if (z < 3) {
            for (int idx = tid; idx < 1024; idx += 256) {
                int kk = idx & 31, mm = idx >> 5;
                As[mm][kk] = wp[(i0 + mm) * 1024 + k0 + kk];
                Bs[mm][kk] = wp[(j0 + mm) * 1024 + k0 + kk];
            }
        } else {
            for (int idx = tid; idx < 1024; idx += 256) {
                int mm = idx & 31, kk = idx >> 5;
                As[mm][kk] = wp[(k0 + kk) * 512 + i0 + mm];
                Bs[mm][kk] = wp[(k0 + kk) * 512 + j0 + mm];
            }
        }
        __syncthreads();
        #pragma unroll
        for (int kk = 0; kk < 32; kk++) {
            float a0 = As[ty][kk], a1 = As[ty + 16][kk];
            float b0 = Bs[tx][kk], b1 = Bs[tx + 16][kk];
            acc[0][0] += a0 * b0; acc[0][1] += a0 * b1;
            acc[1][0] += a1 * b0; acc[1][1] += a1 * b1;
        }
        __syncthreads();
    }
    #pragma unroll
    for (int a = 0; a < 2; a++)
    #pragma unroll
    for (int b = 0; b < 2; b++) {
        int i = i0 + ty + 16 * a, j = j0 + tx + 16 * b;
        float v = acc[a][b];
        d_g0[goff + i * m + j] = v;
        if (i == j) amaxf(&d_maxd[z], v);
    }
}

// H_{t+1} = (H_t / s)^2 ; s = maxdiag(H_t). Symmetric, so H*H == H*H^T (row-row form).
__global__ __launch_bounds__(256) void square_k(int t) {
    int z = blockIdx.z;
    int m = gram_m(z), nt = m >> 5;
    if (blockIdx.x >= nt || blockIdx.y >= nt) return;
    int goff = gram_off(z);
    const float* in = ((t == 0) ? d_g0 : ((t & 1) ? d_ga : d_gb)) + goff;
    float* out = (((t & 1) ? d_gb : d_ga)) + goff;
    float s = __uint_as_float(d_maxd[t * 4 + z]);
    float isc = 1.0f / (s * s);
    int i0 = blockIdx.y * 32, j0 = blockIdx.x * 32;
    int tid = threadIdx.x, tx = tid & 15, ty = tid >> 4;
    __shared__ float As[32][33], Bs[32][33];
    float acc[2][2] = {{0.f,0.f},{0.f,0.f}};
    for (int k0 = 0; k0 < m; k0 += 32) {
        for (int idx = tid; idx < 1024; idx += 256) {
            int kk = idx & 31, mm = idx >> 5;
            As[mm][kk] = in[(i0 + mm) * m + k0 + kk];
            Bs[mm][kk] = in[(j0 + mm) * m + k0 + kk];
        }
        __syncthreads();
        #pragma unroll
        for (int kk = 0; kk < 32; kk++) {
            float a0 = As[ty][kk], a1 = As[ty + 16][kk];
            float b0 = Bs[tx][kk], b1 = Bs[tx + 16][kk];
            acc[0][0] += a0 * b0; acc[0][1] += a0 * b1;
            acc[1][0] += a1 * b0; acc[1][1] += a1 * b1;
        }
        __syncthreads();
    }
    #pragma unroll
    for (int a = 0; a < 2; a++)
    #pragma unroll
    for (int b = 0; b < 2; b++) {
        int i = i0 + ty + 16 * a, j = j0 + tx + 16 * b;
        float v = acc[a][b] * isc;
        out[i * m + j] = v;
        if (i == j) amaxf(&d_maxd[(t + 1) * 4 + z], v);
    }
}

// sigma^2 = (v^T G0 v)/(v^T v) with v = column of H_final at argmax diag.
__global__ void rayleigh_k() {
    int z = blockIdx.x;
    int m = gram_m(z), goff = gram_off(z);
    const float* H  = d_gb + goff;   // NSQ even -> final in d_gb
    const float* G0 = d_g0 + goff;
    int tid = threadIdx.x, lane = tid & 31, w = tid >> 5;
    __shared__ float sval[16]; __shared__ int sidx[16];
    float best = -1.f; int bi = 0;
    for (int i = tid; i < m; i += 512) {
        float d = H[i * m + i];
        if (d > best) { best = d; bi = i; }
    }
    #pragma unroll
    for (int off = 16; off; off >>= 1) {
        float ov = __shfl_xor_sync(0xffffffffu, best, off);
        int   oi = __shfl_xor_sync(0xffffffffu, bi,   off);
        if (ov > best || (ov == best && oi < bi)) { best = ov; bi = oi; }
    }
    if (lane == 0) { sval[w] = best; sidx[w] = bi; }
    __syncthreads();
    if (tid == 0) {
        float bb = sval[0]; int bj = sidx[0];
        for (int i = 1; i < 16; i++)
            if (sval[i] > bb || (sval[i] == bb && sidx[i] < bj)) { bb = sval[i]; bj = sidx[i]; }
        sidx[0] = bj;
    }
    __syncthreads();
    int js = sidx[0];
    __shared__ float sv[512];
    for (int i = tid; i < m; i += 512) sv[i] = H[i * m + js];
    __syncthreads();
    __shared__ float snum[16], sden[16];
    float numacc = 0.f, denacc = 0.f;
    for (int i = w; i < m; i += 16) {
        float u = 0.f;
        for (int j = lane; j < m; j += 32) u += G0[i * m + j] * sv[j];
        #pragma unroll
        for (int off = 16; off; off >>= 1) u += __shfl_xor_sync(0xffffffffu, u, off);
        if (lane == 0) { numacc += sv[i] * u; denacc += sv[i] * sv[i]; }
    }
    if (lane == 0) { snum[w] = numacc; sden[w] = denacc; }
    __syncthreads();
    if (tid == 0) {
        float n = 0.f, d = 0.f;
        for (int i = 0; i < 16; i++) { n += snum[i]; d += sden[i]; }
        d_invsig[z] = sqrtf(d / n);
    }
}

// ---------------- fused theta/phi/g projection: out = (invsig*W) @ src ----------------
__global__ __launch_bounds__(256) void qkv_k(const float* __restrict__ src,
                                             const float* __restrict__ wt,
                                             const float* __restrict__ wf,
                                             const float* __restrict__ wg) {
    int b = blockIdx.z, mt = blockIdx.y;
    const float* wp; float* op; int row0, nrows; float sc;
    if (mt < 2)      { wp = wt; row0 = mt * 64;        sc = d_invsig[0]; op = d_theta;  nrows = C8; }
    else if (mt < 4) { wp = wf; row0 = (mt - 2) * 64;  sc = d_invsig[1]; op = d_phiraw; nrows = C8; }
    else             { wp = wg; row0 = (mt - 4) * 64;  sc = d_invsig[2]; op = d_graw;   nrows = OC; }
    int n0 = blockIdx.x * 64;
    int tid = threadIdx.x, tx = tid & 15, ty = tid >> 4;
    __shared__ float As[16][65], Bs[16][65];
    float acc[4][4] = {};
    const float* sb = src + (size_t)b * CH * WW;
    for (int k0 = 0; k0 < 1024; k0 += 16) {
        for (int idx = tid; idx < 1024; idx += 256) {
            int kk = idx & 15, mm = idx >> 4;
            As[kk][mm] = wp[(row0 + mm) * 1024 + k0 + kk] * sc;
        }
        for (int idx = tid; idx < 1024; idx += 256) {
            int nn = idx & 63, kk = idx >> 6;
            Bs[kk][nn] = sb[(k0 + kk) * WW + n0 + nn];
        }
        __syncthreads();
        #pragma unroll
        for (int kk = 0; kk < 16; kk++) {
            float a[4], bb[4];
            #pragma unroll
            for (int i = 0; i < 4; i++) a[i]  = As[kk][ty + 16 * i];
            #pragma unroll
            for (int j = 0; j < 4; j++) bb[j] = Bs[kk][tx + 16 * j];
            #pragma unroll
            for (int i = 0; i < 4; i++)
            #pragma unroll
            for (int j = 0; j < 4; j++) acc[i][j] += a[i] * bb[j];
        }
        __syncthreads();
    }
    float* ob = op + (size_t)b * nrows * WW;
    #pragma unroll
    for (int i = 0; i < 4; i++)
    #pragma unroll
    for (int j = 0; j < 4; j++)
        ob[(row0 + ty + 16 * i) * WW + n0 + tx + 16 * j] = acc[i][j];
}

// maxpool 2x2 over (c,w); sel 0 = phi (C=128), 1 = g (C=512)
__global__ void pool_k(int sel) {
    int gid = blockIdx.x * 256 + threadIdx.x;
    int inC = sel ? OC : C8;
    const float* in = sel ? d_graw : d_phiraw;
    float* out = sel ? d_gp : d_phip;
    int per = (inC / 2) * PW;
    if (gid >= BB * per) return;
    int b = gid / per, r = gid - b * per;
    int cp = r / PW, wp = r - cp * PW;
    const float* p = in + (size_t)b * inC * WW + (size_t)(2 * cp) * WW + 2 * wp;
    out[gid] = fmaxf(fmaxf(p[0], p[1]), fmaxf(p[WW], p[WW + 1]));
}

// scores S[b,w,v] = sum_c theta[b,c,w] * phip[b, c*512+v]
__global__ __launch_bounds__(256) void scores_k() {
    int b = blockIdx.z;
    int m0 = blockIdx.y * 64, n0 = blockIdx.x * 64;
    int tid = threadIdx.x, tx = tid & 15, ty = tid >> 4;
    const float* tb = d_theta + (size_t)b * C8 * WW;
    const float* pb = d_phip  + (size_t)b * C8 * WP;
    __shared__ float As[16][65], Bs[16][65];
    float acc[4][4] = {};
    for (int k0 = 0; k0 < 128; k0 += 16) {
        for (int idx = tid; idx < 1024; idx += 256) {
            int mm = idx & 63, kk = idx >> 6;
            As[kk][mm] = tb[(k0 + kk) * WW + m0 + mm];
        }
        for (int idx = tid; idx < 1024; idx += 256) {
            int nn = idx & 63, kk = idx >> 6;
            Bs[kk][nn] = pb[(k0 + kk) * WP + n0 + nn];
        }
        __syncthreads();
        #pragma unroll
        for (int kk = 0; kk < 16; kk++) {
            float a[4], bb[4];
            #pragma unroll
            for (int i = 0; i < 4; i++) a[i]  = As[kk][ty + 16 * i];
            #pragma unroll
            for (int j = 0; j < 4; j++) bb[j] = Bs[kk][tx + 16 * j];
            #pragma unroll
            for (int i = 0; i < 4; i++)
            #pragma unroll
            for (int j = 0; j < 4; j++) acc[i][j] += a[i] * bb[j];
        }
        __syncthreads();
    }
    float* ob = d_attn + (size_t)b * WW * WP;
    #pragma unroll
    for (int i = 0; i < 4; i++)
    #pragma unroll
    for (int j = 0; j < 4; j++)
        ob[(m0 + ty + 16 * i) * WP + n0 + tx + 16 * j] = acc[i][j];
}

__global__ __launch_bounds__(128) void softmax_k() {
    int row = blockIdx.x;                 // 0..8191
    float* p = d_attn + (size_t)row * WP;
    int t = threadIdx.x, lane = t & 31, w = t >> 5;
    float v0 = p[t], v1 = p[t + 128], v2 = p[t + 256], v3 = p[t + 384];
    float mx = fmaxf(fmaxf(v0, v1), fmaxf(v2, v3));
    __shared__ float sm[4];
    #pragma unroll
    for (int off = 16; off; off >>= 1) mx = fmaxf(mx, __shfl_xor_sync(0xffffffffu, mx, off));
    if (lane == 0) sm[w] = mx;
    __syncthreads();
    mx = fmaxf(fmaxf(sm[0], sm[1]), fmaxf(sm[2], sm[3]));
    float e0 = expf(v0 - mx), e1 = expf(v1 - mx), e2 = expf(v2 - mx), e3 = expf(v3 - mx);
    float s = e0 + e1 + e2 + e3;
    #pragma unroll
    for (int off = 16; off; off >>= 1) s += __shfl_xor_sync(0xffffffffu, s, off);
    if (lane == 0) sm[w] = s;
    __syncthreads();
    float inv = 1.0f / (sm[0] + sm[1] + sm[2] + sm[3]);
    p[t] = e0 * inv; p[t + 128] = e1 * inv; p[t + 256] = e2 * inv; p[t + 384] = e3 * inv;
}

// attn_g[b,c,w] = sum_v gp[b, c*512+v] * attn[b, w, v]
__global__ __launch_bounds__(256) void attng_k() {
    int b = blockIdx.z;
    int m0 = blockIdx.y * 64, n0 = blockIdx.x * 64;
    int tid = threadIdx.x, tx = tid & 15, ty = tid >> 4;
    const float* gb = d_gp   + (size_t)b * OC * WP;
    const float* ab = d_attn + (size_t)b * WW * WP;
    __shared__ float As[16][65], Bs[16][65];
    float acc[4][4] = {};
    for (int k0 = 0; k0 < WP; k0 += 16) {
        for (int idx = tid; idx < 1024; idx += 256) {
            int kk = idx & 15, mm = idx >> 4;
            As[kk][mm] = gb[(m0 + mm) * WP + k0 + kk];
        }
        for (int idx = tid; idx < 1024; idx += 256) {
            int kk = idx & 15, nn = idx >> 4;
            Bs[kk][nn] = ab[(size_t)(n0 + nn) * WP + k0 + kk];
        }
        __syncthreads();
        #pragma unroll
        for (int kk = 0; kk < 16; kk++) {
            float a[4], bb[4];
            #pragma unroll
            for (int i = 0; i < 4; i++) a[i]  = As[kk][ty + 16 * i];
            #pragma unroll
            for (int j = 0; j < 4; j++) bb[j] = Bs[kk][tx + 16 * j];
            #pragma unroll
            for (int i = 0; i < 4; i++)
            #pragma unroll
            for (int j = 0; j < 4; j++) acc[i][j] += a[i] * bb[j];
        }
        __syncthreads();
    }
    float* ob = d_attng + (size_t)b * OC * WW;
    #pragma unroll
    for (int i = 0; i < 4; i++)
    #pragma unroll
    for (int j = 0; j < 4; j++)
        ob[(m0 + ty + 16 * i) * WW + n0 + tx + 16 * j] = acc[i][j];
}

// x = 2*src + gamma * ( (invsig3 * w_o) @ attn_g )
__global__ __launch_bounds__(256) void xo_k(const float* __restrict__ src,
                                            const float* __restrict__ wo,
                                            const float* __restrict__ gammap) {
    int b = blockIdx.z;
    int m0 = blockIdx.y * 64, n0 = blockIdx.x * 64;
    int tid = threadIdx.x, tx = tid & 15, ty = tid >> 4;
    float sc = d_invsig[3];
    float gm = gammap[0];
    const float* ab = d_attng + (size_t)b * OC * WW;
    __shared__ float As[16][65], Bs[16][65];
    float acc[4][4] = {};
    for (int k0 = 0; k0 < OC; k0 += 16) {
        for (int idx = tid; idx < 1024; idx += 256) {
            int kk = idx & 15, mm = idx >> 4;
            As[kk][mm] = wo[(m0 + mm) * OC + k0 + kk] * sc;
        }
        for (int idx = tid; idx < 1024; idx += 256) {
            int nn = idx & 63, kk = idx >> 6;
            Bs[kk][nn] = ab[(k0 + kk) * WW + n0 + nn];
        }
        __syncthreads();
        #pragma unroll
        for (int kk = 0; kk < 16; kk++) {
            float a[4], bb[4];
            #pragma unroll
            for (int i = 0; i < 4; i++) a[i]  = As[kk][ty + 16 * i];
            #pragma unroll
            for (int j = 0; j < 4; j++) bb[j] = Bs[kk][tx + 16 * j];
            #pragma unroll
            for (int i = 0; i < 4; i++)
            #pragma unroll
            for (int j = 0; j < 4; j++) acc[i][j] += a[i] * bb[j];
        }
        __syncthreads();
    }
    #pragma unroll
    for (int i = 0; i < 4; i++)
    #pragma unroll
    for (int j = 0; j < 4; j++) {
        size_t oi = (size_t)b * CH * WW + (size_t)(m0 + ty + 16 * i) * WW + n0 + tx + 16 * j;
        d_x[oi] = 2.0f * src[oi] + gm * acc[i][j];
    }
}

// conv1d K=3 'same' + ReLU (+ optional residual). insel: 0=d_x 1=d_h1 2=d_h2.
// outsel: 0=d_h1 1=d_h2 2=outext.
__global__ __launch_bounds__(256) void conv_k(int insel, const float* __restrict__ wgt,
                                              const float* __restrict__ bias,
                                              const float* __restrict__ resid,
                                              float* outext, int outsel,
                                              int IC, int OCn) {
    const float* in = (insel == 0) ? d_x : (insel == 1) ? d_h1 : d_h2;
    float* out = (outsel == 0) ? d_h1 : (outsel == 1) ? d_h2 : outext;
    int bz = blockIdx.z;
    int o0 = blockIdx.y * 64, w0 = blockIdx.x * 64;
    int tid = threadIdx.x, tx = tid & 15, ty = tid >> 4;
    __shared__ float xs[16][72];   // 66 used (halo), padded
    __shared__ float ws[64][48];   // 16 ic * 3 taps
    float acc[4][4] = {};
    const float* inb = in + (size_t)bz * IC * WW;
    for (int ic0 = 0; ic0 < IC; ic0 += 16) {
        for (int idx = tid; idx < 16 * 66; idx += 256) {
            int r = idx / 66, c = idx - r * 66;
            int wsrc = w0 + c - 1;
            xs[r][c] = (wsrc >= 0 && wsrc < WW) ? inb[(size_t)(ic0 + r) * WW + wsrc] : 0.0f;
        }
        for (int idx = tid; idx < 64 * 48; idx += 256) {
            int oo = idx / 48, q = idx - oo * 48;
            ws[oo][q] = wgt[(size_t)(o0 + oo) * IC * 3 + ic0 * 3 + q];
        }
        __syncthreads();
        #pragma unroll
        for (int ic = 0; ic < 16; ic++) {
            float wv0[4], wv1[4], wv2[4];
            #pragma unroll
            for (int a = 0; a < 4; a++) {
                wv0[a] = ws[ty + 16 * a][ic * 3 + 0];
                wv1[a] = ws[ty + 16 * a][ic * 3 + 1];
                wv2[a] = ws[ty + 16 * a][ic * 3 + 2];
            }
            #pragma unroll
            for (int b2 = 0; b2 < 4; b2++) {
                float x0 = xs[ic][tx + 16 * b2];
                float x1 = xs[ic][tx + 16 * b2 + 1];
                float x2 = xs[ic][tx + 16 * b2 + 2];
                #pragma unroll
                for (int a = 0; a < 4; a++)
                    acc[a][b2] += wv0[a] * x0 + wv1[a] * x1 + wv2[a] * x2;
            }
        }
        __syncthreads();
    }
    #pragma unroll
    for (int a = 0; a < 4; a++) {
        int o = o0 + ty + 16 * a;
        float bi = bias[o];
        #pragma unroll
        for (int b2 = 0; b2 < 4; b2++) {
            int wi = w0 + tx + 16 * b2;
            float v = fmaxf(acc[a][b2] + bi, 0.0f);
            size_t oi = (size_t)bz * OCn * WW + (size_t)o * WW + wi;
            if (resid) v += resid[oi];
            out[oi] = v;
        }
    }
}

// ---------------- launch ----------------
extern "C" void kernel_launch(void* const* d_in, const int* in_sizes, int n_in,
                              void* d_out, int out_size) {
    const float* src     = (const float*)d_in[0];
    const float* w_theta = (const float*)d_in[1];
    const float* w_phi   = (const float*)d_in[2];
    const float* w_g     = (const float*)d_in[3];
    const float* w_o     = (const float*)d_in[4];
    const float* gamma   = (const float*)d_in[5];
    const float* w_c1    = (const float*)d_in[6];
    const float* b_c1    = (const float*)d_in[7];
    const float* w_c2    = (const float*)d_in[8];
    const float* b_c2    = (const float*)d_in[9];
    const float* w_c3    = (const float*)d_in[10];
    const float* b_c3    = (const float*)d_in[11];
    const float* w_c4    = (const float*)d_in[12];
    const float* b_c4    = (const float*)d_in[13];
    float* out = (float*)d_out;

    // spectral norms
    init_k<<<1, 64>>>();
    gram_k<<<dim3(16, 16, 4), 256>>>(w_theta, w_phi, w_g, w_o);
    for (int t = 0; t < NSQ; t++)
        square_k<<<dim3(16, 16, 4), 256>>>(t);
    rayleigh_k<<<4, 512>>>();

    // attention
    qkv_k<<<dim3(32, 12, 4), 256>>>(src, w_theta, w_phi, w_g);
    pool_k<<<(BB * (C8 / 2) * PW + 255) / 256, 256>>>(0);   // phi
    pool_k<<<(BB * (OC / 2) * PW + 255) / 256, 256>>>(1);   // g
    scores_k<<<dim3(WP / 64, WW / 64, 4), 256>>>();
    softmax_k<<<BB * WW, 128>>>();
    attng_k<<<dim3(WW / 64, OC / 64, 4), 256>>>();
    xo_k<<<dim3(WW / 64, CH / 64, 4), 256>>>(src, w_o, gamma);

    // conv FFN
    conv_k<<<dim3(WW / 64, OC / 64, 4), 256>>>(0, w_c1, b_c1, nullptr, nullptr, 0, CH, OC);
    conv_k<<<dim3(WW / 64, OC / 64, 4), 256>>>(1, w_c2, b_c2, nullptr, nullptr, 1, OC, OC);
    conv_k<<<dim3(WW / 64, OC / 64, 4), 256>>>(2, w_c3, b_c3, nullptr, nullptr, 0, OC, OC);
    conv_k<<<dim3(WW / 64, CH / 64, 4), 256>>>(1, w_c4, b_c4, src, out, 2, OC, CH);
}

// round 14
// speedup vs baseline: 2.1610x; 2.1576x over previous
#include <cuda_runtime.h>
#include <math.h>
#include <stdint.h>

// Problem constants
#define BB 4
#define CH 1024
#define WW 2048
#define OC 512      // CH/2
#define C8 128      // CH/8
#define PW 1024     // pooled width (WW/2)
#define WP 512      // WW/4
#define NSQ 10      // Gram squarings -> exponent 2^10

// ---------------- scratch (static device memory; no allocations) ----------------
__device__ float d_theta [BB*C8*WW];
__device__ float d_phiraw[BB*C8*WW];
__device__ float d_graw  [BB*OC*WW];
__device__ float d_phip  [BB*C8*WP];
__device__ float d_gp    [BB*OC*WP];
__device__ float d_attn  [BB*WW*WP];
__device__ float d_attng [BB*OC*WW];
__device__ float d_x     [BB*CH*WW];
__device__ float d_h1    [BB*OC*WW];
__device__ float d_h2    [BB*OC*WW];

#define GTOT (2*128*128 + 2*512*512)
__device__ float    d_g0[GTOT];
__device__ float    d_ga[GTOT];
__device__ float    d_gb[GTOT];
__device__ unsigned d_maxd[(NSQ+1)*4];
__device__ float    d_invsig[4];

__device__ __forceinline__ int gram_off(int z) {
    return (z == 0) ? 0 : (z == 1) ? 16384 : (z == 2) ? 32768 : 294912;
}
__device__ __forceinline__ void amaxf(unsigned* p, float v) {
    atomicMax(p, __float_as_uint(v));  // valid for non-negative floats
}

// fp32 -> tf32 round-to-nearest (sm_80+; idempotent under mma's tf32 read).
__device__ __forceinline__ float to_tf32_rn(float x) {
    uint32_t r;
    asm("cvt.rna.tf32.f32 %0, %1;" : "=r"(r) : "f"(x));
    return __uint_as_float(r);
}

// ================= mma.sync tf32 GEMM skeleton (sm_80+ path, works at sm_103) ===
// Block 256 thr / 8 warps. BM=BN=128, BK=16. Warp tile 32x64 (warp grid 4x2).
// m16n8k8 fragments per PTX ISA:
//   A: a0=[g][t4] a1=[g+8][t4] a2=[g][t4+4] a3=[g+8][t4+4]
//   B: b0=[t4][g] b1=[t4+4][g]      C: c0=[g][2t4] c1=[g][2t4+1] c2/c3 rows +8
// As[128][20] (pad->conflict-free), Bs[16][136] (pad->conflict-free).

#define A_LD 20
#define B_LD 136

__device__ __forceinline__ void mma8(float* c, const uint32_t* a, uint32_t b0, uint32_t b1) {
    asm volatile(
        "mma.sync.aligned.m16n8k8.row.col.f32.tf32.tf32.f32 "
        "{%0,%1,%2,%3}, {%4,%5,%6,%7}, {%8,%9}, {%0,%1,%2,%3};"
        : "+f"(c[0]), "+f"(c[1]), "+f"(c[2]), "+f"(c[3])
        : "r"(a[0]), "r"(a[1]), "r"(a[2]), "r"(a[3]), "r"(b0), "r"(b1));
}

__device__ __forceinline__ void mma_chunk(const float (*Asm)[A_LD], const float (*Bsm)[B_LD],
                                          float acc[2][8][4], int m0w, int n0w, int g, int t4) {
    #pragma unroll
    for (int ks = 0; ks < 2; ks++) {
        int kb = ks * 8;
        uint32_t a[2][4];
        #pragma unroll
        for (int mi = 0; mi < 2; mi++) {
            int mr = m0w + mi * 16;
            a[mi][0] = __float_as_uint(Asm[mr + g    ][kb + t4    ]);
            a[mi][1] = __float_as_uint(Asm[mr + g + 8][kb + t4    ]);
            a[mi][2] = __float_as_uint(Asm[mr + g    ][kb + t4 + 4]);
            a[mi][3] = __float_as_uint(Asm[mr + g + 8][kb + t4 + 4]);
        }
        #pragma unroll
        for (int nj = 0; nj < 8; nj++) {
            uint32_t b0 = __float_as_uint(Bsm[kb + t4    ][n0w + nj * 8 + g]);
            uint32_t b1 = __float_as_uint(Bsm[kb + t4 + 4][n0w + nj * 8 + g]);
            #pragma unroll
            for (int mi = 0; mi < 2; mi++)
                mma8(acc[mi][nj], a[mi], b0, b1);
        }
    }
}

// A fill: K-contiguous rows src[(row0+row)*ldk + k], optional scale, tf32 RN.
__device__ __forceinline__ void fillA(float (*Asm)[A_LD], const float* src, size_t ldk,
                                      int row0, int kg0, int tid, float sc) {
    int row = tid >> 1, half = tid & 1;
    const float* ar = src + (size_t)(row0 + row) * ldk + kg0 + half * 8;
    float4 v0 = *(const float4*)ar;
    float4 v1 = *(const float4*)(ar + 4);
    float* d = &Asm[row][half * 8];
    *(float4*)d = make_float4(to_tf32_rn(v0.x * sc), to_tf32_rn(v0.y * sc),
                              to_tf32_rn(v0.z * sc), to_tf32_rn(v0.w * sc));
    *(float4*)(d + 4) = make_float4(to_tf32_rn(v1.x * sc), to_tf32_rn(v1.y * sc),
                                    to_tf32_rn(v1.z * sc), to_tf32_rn(v1.w * sc));
}
// B fill, source already [k][n] (n contiguous): direct copy rows.
__device__ __forceinline__ void fillB_direct(float (*Bsm)[B_LD], const float* src, size_t ldn,
                                             int n0, int kg0, int tid) {
    int k = tid >> 4, seg = tid & 15;
    const float* br = src + (size_t)(kg0 + k) * ldn + n0 + seg * 8;
    float4 v0 = *(const float4*)br;
    float4 v1 = *(const float4*)(br + 4);
    float* d = &Bsm[k][seg * 8];
    *(float4*)d = make_float4(to_tf32_rn(v0.x), to_tf32_rn(v0.y),
                              to_tf32_rn(v0.z), to_tf32_rn(v0.w));
    *(float4*)(d + 4) = make_float4(to_tf32_rn(v1.x), to_tf32_rn(v1.y),
                                    to_tf32_rn(v1.z), to_tf32_rn(v1.w));
}
// B fill, source [n][k] (k contiguous): transpose into Bs[k][n].
__device__ __forceinline__ void fillB_trans(float (*Bsm)[B_LD], const float* src, size_t ldk,
                                            int n0, int kg0, int tid) {
    int n = tid & 127, kh = tid >> 7;
    const float* ar = src + (size_t)(n0 + n) * ldk + kg0 + kh * 8;
    float4 v0 = *(const float4*)ar;
    float4 v1 = *(const float4*)(ar + 4);
    int kb = kh * 8;
    Bsm[kb + 0][n] = to_tf32_rn(v0.x);
    Bsm[kb + 1][n] = to_tf32_rn(v0.y);
    Bsm[kb + 2][n] = to_tf32_rn(v0.z);
    Bsm[kb + 3][n] = to_tf32_rn(v0.w);
    Bsm[kb + 4][n] = to_tf32_rn(v1.x);
    Bsm[kb + 5][n] = to_tf32_rn(v1.y);
    Bsm[kb + 6][n] = to_tf32_rn(v1.z);
    Bsm[kb + 7][n] = to_tf32_rn(v1.w);
}
// B fill for conv im2col: B[k=(ic,t)][n=w] = x[ic][w0+n+t-1], clamped.
__device__ __forceinline__ void fillB_conv(float (*Bsm)[B_LD], const float* xb,
                                           int w0, int kg0, int tid) {
    int k = tid >> 4, seg = tid & 15;
    int kg = kg0 + k, ic = kg / 3, ts = kg - ic * 3;
    const float* xr = xb + (size_t)ic * WW;
    int wb = w0 + seg * 8 + ts - 1;
    float t[8];
    #pragma unroll
    for (int q = 0; q < 8; q++) {
        int ws = wb + q;
        t[q] = ((unsigned)ws < (unsigned)WW) ? xr[ws] : 0.0f;
    }
    float* d = &Bsm[k][seg * 8];
    *(float4*)d = make_float4(to_tf32_rn(t[0]), to_tf32_rn(t[1]),
                              to_tf32_rn(t[2]), to_tf32_rn(t[3]));
    *(float4*)(d + 4) = make_float4(to_tf32_rn(t[4]), to_tf32_rn(t[5]),
                                    to_tf32_rn(t[6]), to_tf32_rn(t[7]));
}

#define MMA_VARS() \
    int tid = threadIdx.x, lane = tid & 31, wid = tid >> 5; \
    int g = lane >> 2, t4 = lane & 3; \
    int m0w = (wid & 3) * 32, n0w = (wid >> 2) * 64; \
    float acc[2][8][4] = {};

// ---------------- spectral norm chain ----------------
__global__ void init_k() {
    int t = threadIdx.x;
    if (t < (NSQ + 1) * 4) d_maxd[t] = 0u;
}

__device__ __forceinline__ void spec_map(int bid, int& z, int& i0, int& j0, int& m) {
    if (bid < 4)       { z = 0; i0 = (bid >> 1) * 64;        j0 = (bid & 1) * 64;        m = 128; }
    else if (bid < 8)  { z = 1; i0 = ((bid - 4) >> 1) * 64;  j0 = ((bid - 4) & 1) * 64;  m = 128; }
    else if (bid < 72) { z = 2; i0 = ((bid - 8) >> 3) * 64;  j0 = ((bid - 8) & 7) * 64;  m = 512; }
    else               { z = 3; i0 = ((bid - 72) >> 3) * 64; j0 = ((bid - 72) & 7) * 64; m = 512; }
}

__global__ __launch_bounds__(256) void gram64_k(const float* w0_, const float* w1_,
                                                const float* w2_, const float* w3_) {
    int z, i0, j0, m;
    spec_map(blockIdx.x, z, i0, j0, m);
    const float* wp = (z == 0) ? w0_ : (z == 1) ? w1_ : (z == 2) ? w2_ : w3_;
    int goff = gram_off(z);
    int tid = threadIdx.x, tx = tid & 15, ty = tid >> 4;
    __shared__ float As[16][65], Bs[16][65];
    float acc[4][4] = {};
    for (int k0 = 0; k0 < 1024; k0 += 16) {
        if (z < 3) {
            for (int idx = tid; idx < 1024; idx += 256) {
                int kk = idx & 15, mm = idx >> 4;
                As[kk][mm] = wp[(i0 + mm) * 1024 + k0 + kk];
                Bs[kk][mm] = wp[(j0 + mm) * 1024 + k0 + kk];
            }
        } else {
            for (int idx = tid; idx < 1024; idx += 256) {
                int mm = idx & 63, kk = idx >> 6;
                As[kk][mm] = wp[(k0 + kk) * 512 + i0 + mm];
                Bs[kk][mm] = wp[(k0 + kk) * 512 + j0 + mm];
            }
        }
        __syncthreads();
        #pragma unroll
        for (int kk = 0; kk < 16; kk++) {
            float a[4], bb[4];
            #pragma unroll
            for (int i = 0; i < 4; i++) a[i]  = As[kk][ty + 16 * i];
            #pragma unroll
            for (int j = 0; j < 4; j++) bb[j] = Bs[kk][tx + 16 * j];
            #pragma unroll
            for (int i = 0; i < 4; i++)
            #pragma unroll
            for (int j = 0; j < 4; j++) acc[i][j] += a[i] * bb[j];
        }
        __syncthreads();
    }
    #pragma unroll
    for (int a = 0; a < 4; a++)
    #pragma unroll
    for (int b = 0; b < 4; b++) {
        int i = i0 + ty + 16 * a, j = j0 + tx + 16 * b;
        float v = acc[a][b];
        d_g0[goff + i * m + j] = v;
        if (i == j) amaxf(&d_maxd[z], v);
    }
}

__global__ __launch_bounds__(256) void square64_k(int t) {
    int z, i0, j0, m;
    spec_map(blockIdx.x, z, i0, j0, m);
    int goff = gram_off(z);
    const float* in = ((t == 0) ? d_g0 : ((t & 1) ? d_ga : d_gb)) + goff;
    float* out = (((t & 1) ? d_gb : d_ga)) + goff;
    float s = __uint_as_float(d_maxd[t * 4 + z]);
    float isc = 1.0f / (s * s);
    int tid = threadIdx.x, tx = tid & 15, ty = tid >> 4;
    __shared__ float As[16][65], Bs[16][65];
    float acc[4][4] = {};
    for (int k0 = 0; k0 < m; k0 += 16) {
        for (int idx = tid; idx < 1024; idx += 256) {
            int mm = idx & 63, kk = idx >> 6;
            As[kk][mm] = in[(k0 + kk) * m + i0 + mm];
            Bs[kk][mm] = in[(k0 + kk) * m + j0 + mm];
        }
        __syncthreads();
        #pragma unroll
        for (int kk = 0; kk < 16; kk++) {
            float a[4], bb[4];
            #pragma unroll
            for (int i = 0; i < 4; i++) a[i]  = As[kk][ty + 16 * i];
            #pragma unroll
            for (int j = 0; j < 4; j++) bb[j] = Bs[kk][tx + 16 * j];
            #pragma unroll
            for (int i = 0; i < 4; i++)
            #pragma unroll
            for (int j = 0; j < 4; j++) acc[i][j] += a[i] * bb[j];
        }
        __syncthreads();
    }
    #pragma unroll
    for (int a = 0; a < 4; a++)
    #pragma unroll
    for (int b = 0; b < 4; b++) {
        int i = i0 + ty + 16 * a, j = j0 + tx + 16 * b;
        float v = acc[a][b] * isc;
        out[i * m + j] = v;
        if (i == j) amaxf(&d_maxd[(t + 1) * 4 + z], v);
    }
}

__global__ void rayleigh_k() {
    int z = blockIdx.x;
    int m = (z < 2) ? 128 : 512, goff = gram_off(z);
    const float* H  = d_gb + goff;   // NSQ even -> final in d_gb
    const float* G0 = d_g0 + goff;
    int tid = threadIdx.x, lane = tid & 31, w = tid >> 5;
    __shared__ float sval[16]; __shared__ int sidx[16];
    float best = -1.f; int bi = 0;
    for (int i = tid; i < m; i += 512) {
        float d = H[i * m + i];
        if (d > best) { best = d; bi = i; }
    }
    #pragma unroll
    for (int off = 16; off; off >>= 1) {
        float ov = __shfl_xor_sync(0xffffffffu, best, off);
        int   oi = __shfl_xor_sync(0xffffffffu, bi,   off);
        if (ov > best || (ov == best && oi < bi)) { best = ov; bi = oi; }
    }
    if (lane == 0) { sval[w] = best; sidx[w] = bi; }
    __syncthreads();
    if (tid == 0) {
        float bb = sval[0]; int bj = sidx[0];
        for (int i = 1; i < 16; i++)
            if (sval[i] > bb || (sval[i] == bb && sidx[i] < bj)) { bb = sval[i]; bj = sidx[i]; }
        sidx[0] = bj;
    }
    __syncthreads();
    int js = sidx[0];
    __shared__ float sv[512];
    for (int i = tid; i < m; i += 512) sv[i] = H[i * m + js];
    __syncthreads();
    __shared__ float snum[16], sden[16];
    float numacc = 0.f, denacc = 0.f;
    for (int i = w; i < m; i += 16) {
        float u = 0.f;
        for (int j = lane; j < m; j += 32) u += G0[i * m + j] * sv[j];
        #pragma unroll
        for (int off = 16; off; off >>= 1) u += __shfl_xor_sync(0xffffffffu, u, off);
        if (lane == 0) { numacc += sv[i] * u; denacc += sv[i] * sv[i]; }
    }
    if (lane == 0) { snum[w] = numacc; sden[w] = denacc; }
    __syncthreads();
    if (tid == 0) {
        float n = 0.f, d = 0.f;
        for (int i = 0; i < 16; i++) { n += snum[i]; d += sden[i]; }
        d_invsig[z] = sqrtf(d / n);
    }
}

// ================= tf32 mma.sync GEMM kernels =================

// qkv: out[row][w] = invsig * W[row] . src[:, w]; y-tiles: theta, phi, g0..g3.
__global__ __launch_bounds__(256) void qkv_mma_k(const float* __restrict__ src,
                                                 const float* __restrict__ wt,
                                                 const float* __restrict__ wf,
                                                 const float* __restrict__ wg) {
    __shared__ __align__(16) float As[128][A_LD];
    __shared__ __align__(16) float Bs[16][B_LD];
    int b = blockIdx.z, mt = blockIdx.y;
    const float* wp; float* op; int row0; float sc;
    if (mt == 0)      { wp = wt; op = d_theta;  row0 = 0;              sc = d_invsig[0]; }
    else if (mt == 1) { wp = wf; op = d_phiraw; row0 = 0;              sc = d_invsig[1]; }
    else              { wp = wg; op = d_graw;   row0 = (mt - 2) * 128; sc = d_invsig[2]; }
    int n0 = blockIdx.x * 128;
    const float* sbp = src + (size_t)b * CH * WW;
    MMA_VARS();
    for (int kg0 = 0; kg0 < 1024; kg0 += 16) {
        fillA(As, wp, 1024, row0, kg0, tid, sc);
        fillB_direct(Bs, sbp, WW, n0, kg0, tid);
        __syncthreads();
        mma_chunk(As, Bs, acc, m0w, n0w, g, t4);
        __syncthreads();
    }
    float* ob = op + (size_t)b * ((mt < 2) ? C8 : OC) * WW;
    #pragma unroll
    for (int mi = 0; mi < 2; mi++)
    #pragma unroll
    for (int nj = 0; nj < 8; nj++) {
        int m = row0 + m0w + mi * 16 + g;
        int n = n0 + n0w + nj * 8 + t4 * 2;
        *(float2*)(ob + (size_t)m * WW + n)       = make_float2(acc[mi][nj][0], acc[mi][nj][1]);
        *(float2*)(ob + (size_t)(m + 8) * WW + n) = make_float2(acc[mi][nj][2], acc[mi][nj][3]);
    }
}

// attng: out[c][w] = sum_v gp[c][v] * attn[w][v]  (B = attn is [n][k] -> transpose fill)
__global__ __launch_bounds__(256) void attng_mma_k() {
    __shared__ __align__(16) float As[128][A_LD];
    __shared__ __align__(16) float Bs[16][B_LD];
    int b = blockIdx.z;
    int m0 = blockIdx.y * 128, n0 = blockIdx.x * 128;
    const float* gb = d_gp   + (size_t)b * OC * WP;
    const float* ab = d_attn + (size_t)b * WW * WP;
    MMA_VARS();
    for (int kg0 = 0; kg0 < WP; kg0 += 16) {
        fillA(As, gb, WP, m0, kg0, tid, 1.0f);
        fillB_trans(Bs, ab, WP, n0, kg0, tid);
        __syncthreads();
        mma_chunk(As, Bs, acc, m0w, n0w, g, t4);
        __syncthreads();
    }
    float* ob = d_attng + (size_t)b * OC * WW;
    #pragma unroll
    for (int mi = 0; mi < 2; mi++)
    #pragma unroll
    for (int nj = 0; nj < 8; nj++) {
        int m = m0 + m0w + mi * 16 + g;
        int n = n0 + n0w + nj * 8 + t4 * 2;
        *(float2*)(ob + (size_t)m * WW + n)       = make_float2(acc[mi][nj][0], acc[mi][nj][1]);
        *(float2*)(ob + (size_t)(m + 8) * WW + n) = make_float2(acc[mi][nj][2], acc[mi][nj][3]);
    }
}

// xo: x[ch][w] = 2*src[ch][w] + gamma * (invsig3*wo[ch]) . attng[:, w]
__global__ __launch_bounds__(256) void xo_mma_k(const float* __restrict__ src,
                                                const float* __restrict__ wo,
                                                const float* __restrict__ gammap) {
    __shared__ __align__(16) float As[128][A_LD];
    __shared__ __align__(16) float Bs[16][B_LD];
    int b = blockIdx.z;
    int m0 = blockIdx.y * 128, n0 = blockIdx.x * 128;
    float sc = d_invsig[3];
    const float* ab = d_attng + (size_t)b * OC * WW;
    MMA_VARS();
    for (int kg0 = 0; kg0 < OC; kg0 += 16) {
        fillA(As, wo, OC, m0, kg0, tid, sc);
        fillB_direct(Bs, ab, WW, n0, kg0, tid);
        __syncthreads();
        mma_chunk(As, Bs, acc, m0w, n0w, g, t4);
        __syncthreads();
    }
    float gm = gammap[0];
    size_t ob = (size_t)b * CH * WW;
    #pragma unroll
    for (int mi = 0; mi < 2; mi++)
    #pragma unroll
    for (int nj = 0; nj < 8; nj++) {
        int m = m0 + m0w + mi * 16 + g;
        int n = n0 + n0w + nj * 8 + t4 * 2;
        size_t o0i = ob + (size_t)m * WW + n;
        size_t o1i = ob + (size_t)(m + 8) * WW + n;
        float2 s0 = *(const float2*)(src + o0i);
        float2 s1 = *(const float2*)(src + o1i);
        *(float2*)(d_x + o0i) = make_float2(2.0f * s0.x + gm * acc[mi][nj][0],
                                            2.0f * s0.y + gm * acc[mi][nj][1]);
        *(float2*)(d_x + o1i) = make_float2(2.0f * s1.x + gm * acc[mi][nj][2],
                                            2.0f * s1.y + gm * acc[mi][nj][3]);
    }
}

// conv1d K=3: D[o][w] = relu(bias[o] + sum W[o][ic][t]*x[ic][w+t-1]) (+resid)
__global__ __launch_bounds__(256) void conv_mma_k(int insel, const float* __restrict__ wgt,
                                                  const float* __restrict__ bias,
                                                  const float* __restrict__ resid,
                                                  float* __restrict__ outext, int outsel,
                                                  int IC, int OCn) {
    __shared__ __align__(16) float As[128][A_LD];
    __shared__ __align__(16) float Bs[16][B_LD];
    const float* in = (insel == 0) ? d_x : (insel == 1) ? d_h1 : d_h2;
    float* outp = (outsel == 0) ? d_h1 : (outsel == 1) ? d_h2 : outext;
    int bz = blockIdx.z;
    int o0 = blockIdx.y * 128, w0 = blockIdx.x * 128;
    int Ktot = IC * 3;
    const float* xb = in + (size_t)bz * IC * WW;
    MMA_VARS();
    for (int kg0 = 0; kg0 < Ktot; kg0 += 16) {
        fillA(As, wgt, Ktot, o0, kg0, tid, 1.0f);
        fillB_conv(Bs, xb, w0, kg0, tid);
        __syncthreads();
        mma_chunk(As, Bs, acc, m0w, n0w, g, t4);
        __syncthreads();
    }
    size_t ob = (size_t)bz * OCn * WW;
    const float* rb = resid ? (resid + ob) : (const float*)0;
    #pragma unroll
    for (int mi = 0; mi < 2; mi++)
    #pragma unroll
    for (int nj = 0; nj < 8; nj++) {
        int m = o0 + m0w + mi * 16 + g;
        int n = w0 + n0w + nj * 8 + t4 * 2;
        float bi0 = bias[m], bi1 = bias[m + 8];
        float2 v0 = make_float2(fmaxf(acc[mi][nj][0] + bi0, 0.f),
                                fmaxf(acc[mi][nj][1] + bi0, 0.f));
        float2 v1 = make_float2(fmaxf(acc[mi][nj][2] + bi1, 0.f),
                                fmaxf(acc[mi][nj][3] + bi1, 0.f));
        size_t r0 = (size_t)m * WW + n;
        size_t r1 = (size_t)(m + 8) * WW + n;
        if (rb) {
            float2 q0 = *(const float2*)(rb + r0);
            float2 q1 = *(const float2*)(rb + r1);
            v0.x += q0.x; v0.y += q0.y; v1.x += q1.x; v1.y += q1.y;
        }
        *(float2*)(outp + ob + r0) = v0;
        *(float2*)(outp + ob + r1) = v1;
    }
}

// ---------------- SIMT: pool / scores / softmax ----------------
__global__ void pool_k(int sel) {
    int gid = blockIdx.x * 256 + threadIdx.x;
    int inC = sel ? OC : C8;
    const float* in = sel ? d_graw : d_phiraw;
    float* out = sel ? d_gp : d_phip;
    int per = (inC / 2) * PW;
    if (gid >= BB * per) return;
    int b = gid / per, r = gid - b * per;
    int cp = r / PW, wp = r - cp * PW;
    const float* p = in + (size_t)b * inC * WW + (size_t)(2 * cp) * WW + 2 * wp;
    out[gid] = fmaxf(fmaxf(p[0], p[1]), fmaxf(p[WW], p[WW + 1]));
}

__global__ __launch_bounds__(256) void scores_k() {
    int b = blockIdx.z;
    int m0 = blockIdx.y * 64, n0 = blockIdx.x * 64;
    int tid = threadIdx.x, tx = tid & 15, ty = tid >> 4;
    const float* tb = d_theta + (size_t)b * C8 * WW;
    const float* pb = d_phip  + (size_t)b * C8 * WP;
    __shared__ float As[16][65], Bs[16][65];
    float acc[4][4] = {};
    for (int k0 = 0; k0 < 128; k0 += 16) {
        for (int idx = tid; idx < 1024; idx += 256) {
            int mm = idx & 63, kk = idx >> 6;
            As[kk][mm] = tb[(k0 + kk) * WW + m0 + mm];
        }
        for (int idx = tid; idx < 1024; idx += 256) {
            int nn = idx & 63, kk = idx >> 6;
            Bs[kk][nn] = pb[(k0 + kk) * WP + n0 + nn];
        }
        __syncthreads();
        #pragma unroll
        for (int kk = 0; kk < 16; kk++) {
            float a[4], bb[4];
            #pragma unroll
            for (int i = 0; i < 4; i++) a[i]  = As[kk][ty + 16 * i];
            #pragma unroll
            for (int j = 0; j < 4; j++) bb[j] = Bs[kk][tx + 16 * j];
            #pragma unroll
            for (int i = 0; i < 4; i++)
            #pragma unroll
            for (int j = 0; j < 4; j++) acc[i][j] += a[i] * bb[j];
        }
        __syncthreads();
    }
    float* ob = d_attn + (size_t)b * WW * WP;
    #pragma unroll
    for (int i = 0; i < 4; i++)
    #pragma unroll
    for (int j = 0; j < 4; j++)
        ob[(m0 + ty + 16 * i) * WP + n0 + tx + 16 * j] = acc[i][j];
}

__global__ __launch_bounds__(128) void softmax_k() {
    int row = blockIdx.x;
    float* p = d_attn + (size_t)row * WP;
    int t = threadIdx.x, lane = t & 31, w = t >> 5;
    float v0 = p[t], v1 = p[t + 128], v2 = p[t + 256], v3 = p[t + 384];
    float mx = fmaxf(fmaxf(v0, v1), fmaxf(v2, v3));
    __shared__ float sm[4];
    #pragma unroll
    for (int off = 16; off; off >>= 1) mx = fmaxf(mx, __shfl_xor_sync(0xffffffffu, mx, off));
    if (lane == 0) sm[w] = mx;
    __syncthreads();
    mx = fmaxf(fmaxf(sm[0], sm[1]), fmaxf(sm[2], sm[3]));
    float e0 = expf(v0 - mx), e1 = expf(v1 - mx), e2 = expf(v2 - mx), e3 = expf(v3 - mx);
    float s = e0 + e1 + e2 + e3;
    #pragma unroll
    for (int off = 16; off; off >>= 1) s += __shfl_xor_sync(0xffffffffu, s, off);
    if (lane == 0) sm[w] = s;
    __syncthreads();
    float inv = 1.0f / (sm[0] + sm[1] + sm[2] + sm[3]);
    p[t] = e0 * inv; p[t + 128] = e1 * inv; p[t + 256] = e2 * inv; p[t + 384] = e3 * inv;
}

// ---------------- launch ----------------
extern "C" void kernel_launch(void* const* d_in, const int* in_sizes, int n_in,
                              void* d_out, int out_size) {
    const float* src     = (const float*)d_in[0];
    const float* w_theta = (const float*)d_in[1];
    const float* w_phi   = (const float*)d_in[2];
    const float* w_g     = (const float*)d_in[3];
    const float* w_o     = (const float*)d_in[4];
    const float* gamma   = (const float*)d_in[5];
    const float* w_c1    = (const float*)d_in[6];
    const float* b_c1    = (const float*)d_in[7];
    const float* w_c2    = (const float*)d_in[8];
    const float* b_c2    = (const float*)d_in[9];
    const float* w_c3    = (const float*)d_in[10];
    const float* b_c3    = (const float*)d_in[11];
    const float* w_c4    = (const float*)d_in[12];
    const float* b_c4    = (const float*)d_in[13];
    float* out = (float*)d_out;

    // spectral norms
    init_k<<<1, 64>>>();
    gram64_k<<<136, 256>>>(w_theta, w_phi, w_g, w_o);
    for (int t = 0; t < NSQ; t++)
        square64_k<<<136, 256>>>(t);
    rayleigh_k<<<4, 512>>>();

    // attention (tf32 mma.sync for big GEMMs; scores/softmax stay fp32 SIMT)
    qkv_mma_k<<<dim3(16, 6, 4), 256>>>(src, w_theta, w_phi, w_g);
    pool_k<<<(BB * (C8 / 2) * PW + 255) / 256, 256>>>(0);
    pool_k<<<(BB * (OC / 2) * PW + 255) / 256, 256>>>(1);
    scores_k<<<dim3(WP / 64, WW / 64, 4), 256>>>();
    softmax_k<<<BB * WW, 128>>>();
    attng_mma_k<<<dim3(16, 4, 4), 256>>>();
    xo_mma_k<<<dim3(16, 8, 4), 256>>>(src, w_o, gamma);

    // conv FFN on tensor cores (tf32 mma.sync)
    conv_mma_k<<<dim3(16, 4, 4), 256>>>(0, w_c1, b_c1, nullptr, nullptr, 0, CH, OC);
    conv_mma_k<<<dim3(16, 4, 4), 256>>>(1, w_c2, b_c2, nullptr, nullptr, 1, OC, OC);
    conv_mma_k<<<dim3(16, 4, 4), 256>>>(2, w_c3, b_c3, nullptr, nullptr, 0, OC, OC);
    conv_mma_k<<<dim3(16, 8, 4), 256>>>(1, w_c4, b_c4, src, out, 2, OC, CH);
}